// round 15
// baseline (speedup 1.0000x reference)
#include <cuda_runtime.h>
#include <cuda_fp16.h>
#include <cuda_bf16.h>

// Rule-indexed sparse graph convolution, round 15 (= R10 + slot prefetch ONLY).
//   out[n,k,f] = sum_{e: src(e)=n} W[k, lab[src], lab[dst], prop(e)] * x[dst(e), f]
//              + b[k, lab[n], f]
//
// Pipeline (2 launches):
//  1. k_prep_scatter : bucket edges by src (packed rule<<20 | d*32),
//                      transpose Param_W -> float4 PwT, x -> fp16 mirror.
//  2. k_gather : block = 64 = ONE node, 2 warps split the edges (alternating
//                int4 slot groups). Per-edge loads INTERLEAVED with FMA blocks
//                (R10 schedule; front-batching falsified in R13). The ONLY
//                change vs R10: next slot group prefetched one iteration ahead,
//                removing the slot->decode->x serialization at loop boundaries.
//
// fp16 x path measured at rel_err 1.98e-4 (gate 1e-3).

#define KC 4
#define LC 50
#define PC 16
#define FC 128
#define NN 20000
#define EE 640000
#define LLP (LC * LC * PC)    // 40000, k-stride in Param_W
#define NRULE (LC * LC * PC)  // 40000 rules: (lv*L+lw)*P+p
#define CAP 128               // slots/node; Poisson(32) -> overflow prob ~1e-35
#define NF4 (NN * FC / 4)     // 640000 float4s in x

// ---------- static scratch (allocation-free, zero-initialized) ----------
__device__ int    g_cursor[NN];                    // self-resetting (see k_gather)
__device__ __align__(16) int    g_slot[NN * CAP];  // packed (rule<<20) | (d*32)
__device__ float4 g_PwT[NRULE];                    // {w_k0,w_k1,w_k2,w_k3} per rule
__device__ __align__(16) __half g_xh[NN * FC];     // fp16 mirror of x (5 MB)

// ---------- phase 1: scatter + weight transpose + x->fp16 ----------
__global__ void __launch_bounds__(256)
k_prep_scatter(const int*   __restrict__ edge_src,
               const int*   __restrict__ edge_dst,
               const int*   __restrict__ edge_prop,
               const int*   __restrict__ labels,
               const float* __restrict__ Pw,
               const float* __restrict__ x,
               int E) {
    int t = blockIdx.x * blockDim.x + threadIdx.x;   // grid covers 640000

    // x -> fp16 mirror: float4 -> uint2 of 4 halves, fully coalesced
    if (t < NF4) {
        float4 v = __ldg(&((const float4*)x)[t]);
        __half2 h0 = __floats2half2_rn(v.x, v.y);
        __half2 h1 = __floats2half2_rn(v.z, v.w);
        uint2 pk;
        pk.x = *(unsigned int*)&h0;
        pk.y = *(unsigned int*)&h1;
        ((uint2*)g_xh)[t] = pk;
    }

    // Param_W transpose into float4-per-rule
    if (t < NRULE / 4) {
        const float4* Pw4 = (const float4*)Pw;
        float4 w0 = __ldg(&Pw4[t]);                 // k=0
        float4 w1 = __ldg(&Pw4[t + LLP / 4]);       // k=1
        float4 w2 = __ldg(&Pw4[t + 2 * LLP / 4]);   // k=2
        float4 w3 = __ldg(&Pw4[t + 3 * LLP / 4]);   // k=3
        int b = t * 4;
        g_PwT[b + 0] = make_float4(w0.x, w1.x, w2.x, w3.x);
        g_PwT[b + 1] = make_float4(w0.y, w1.y, w2.y, w3.y);
        g_PwT[b + 2] = make_float4(w0.z, w1.z, w2.z, w3.z);
        g_PwT[b + 3] = make_float4(w0.w, w1.w, w2.w, w3.w);
    }

    // edge bucketing (cursors start at zero via the self-reset invariant)
    if (t < E) {
        int s  = edge_src[t];
        int d  = edge_dst[t];
        int p  = edge_prop[t];
        int lw = __ldg(&labels[d]);
        // rule<<20 | d*32 : rule < 800 (10b), d*32 < 640000 (20b)
        int pk = ((lw * PC + p) << 20) | (d << 5);
        int pos = atomicAdd(&g_cursor[s], 1);
        if (pos < CAP) g_slot[s * CAP + pos] = pk;
    }
}

// ---------- phase 2: gather, block = one node, 2 edge-split warps ----------
__global__ void __launch_bounds__(64, 24)
k_gather(const int*   __restrict__ labels,
         const float* __restrict__ Pb,
         float*       __restrict__ out) {
    int tid  = threadIdx.x;
    int lane = tid & 31;
    int half = tid >> 5;               // 0 or 1
    int n    = blockIdx.x;             // grid = NN, exact

    __shared__ float4 sacc[4][32];     // [channel][lane], 2 KB

    int lv  = labels[n];               // uniform per warp
    int cnt = g_cursor[n];
    if (cnt > CAP) cnt = CAP;

    const int4*  slots4 = (const int4*)(g_slot + n * CAP);   // 16B aligned
    const uint2* xh     = (const uint2*)g_xh + lane;  // + (d*32) per row

    float4 a0 = make_float4(0.f, 0.f, 0.f, 0.f);
    float4 a1 = a0, a2 = a0, a3 = a0;

    const float4* PwTlv = g_PwT + lv * (LC * PC);   // + (lw*PC+p)

#define ACC_EDGE(W, RAW)                                                        \
    {                                                                           \
        float2 lo = __half22float2(*(__half2*)&(RAW).x);                        \
        float2 hi = __half22float2(*(__half2*)&(RAW).y);                        \
        a0.x += (W).x * lo.x; a0.y += (W).x * lo.y; a0.z += (W).x * hi.x; a0.w += (W).x * hi.y; \
        a1.x += (W).y * lo.x; a1.y += (W).y * lo.y; a1.z += (W).y * hi.x; a1.w += (W).y * hi.y; \
        a2.x += (W).z * lo.x; a2.y += (W).z * lo.y; a2.z += (W).z * hi.x; a2.w += (W).z * hi.y; \
        a3.x += (W).w * lo.x; a3.y += (W).w * lo.y; a3.z += (W).w * hi.x; a3.w += (W).w * hi.y; \
    }

    int nG = cnt >> 2;                 // int4 groups of 4 edges
    int g  = half;
    int4 pk = (g < nG) ? slots4[g] : make_int4(0, 0, 0, 0);
    while (g < nG) {
        int4 cur = pk;
        int gn = g + 2;
        if (gn < nG) pk = slots4[gn];           // prefetch next slot group

        int o0 = cur.x & 0xFFFFF; unsigned r0 = ((unsigned)cur.x) >> 20;
        int o1 = cur.y & 0xFFFFF; unsigned r1 = ((unsigned)cur.y) >> 20;
        int o2 = cur.z & 0xFFFFF; unsigned r2 = ((unsigned)cur.z) >> 20;
        int o3 = cur.w & 0xFFFFF; unsigned r3 = ((unsigned)cur.w) >> 20;

        // R10 interleaved schedule: one broadcast + one random load + one FMA
        // block per edge. (Front-batching the 4 random loads regressed, R13.)
        float4 w0 = __ldg(&PwTlv[r0]);
        uint2  v0 = __ldg(&xh[o0]);
        ACC_EDGE(w0, v0)
        float4 w1 = __ldg(&PwTlv[r1]);
        uint2  v1 = __ldg(&xh[o1]);
        ACC_EDGE(w1, v1)
        float4 w2 = __ldg(&PwTlv[r2]);
        uint2  v2 = __ldg(&xh[o2]);
        ACC_EDGE(w2, v2)
        float4 w3 = __ldg(&PwTlv[r3]);
        uint2  v3 = __ldg(&xh[o3]);
        ACC_EDGE(w3, v3)

        g = gn;
    }
    if (half == 1) {                   // tail edges (cnt % 4) handled by warp 1
        for (int i = nG << 2; i < cnt; ++i) {
            int pw = g_slot[n * CAP + i];
            int o0 = pw & 0xFFFFF; unsigned r0 = ((unsigned)pw) >> 20;
            float4 w0 = __ldg(&PwTlv[r0]);
            uint2  v0 = __ldg(&xh[o0]);
            ACC_EDGE(w0, v0)
        }
    }
#undef ACC_EDGE

    // Combine: warp 1 -> smem, sync, warp 0 adds + bias + stores.
    if (half == 1) {
        sacc[0][lane] = a0;
        sacc[1][lane] = a1;
        sacc[2][lane] = a2;
        sacc[3][lane] = a3;
    }
    __syncthreads();

    if (half == 0) {
        float4 p0 = sacc[0][lane];
        float4 p1 = sacc[1][lane];
        float4 p2 = sacc[2][lane];
        float4 p3 = sacc[3][lane];

        const float4* pb = (const float4*)Pb;
        float4*       o  = (float4*)(out + (size_t)n * (KC * FC));

        float4 b0 = __ldg(&pb[(0 * LC + lv) * (FC / 4) + lane]);
        float4 b1 = __ldg(&pb[(1 * LC + lv) * (FC / 4) + lane]);
        float4 b2 = __ldg(&pb[(2 * LC + lv) * (FC / 4) + lane]);
        float4 b3 = __ldg(&pb[(3 * LC + lv) * (FC / 4) + lane]);

        a0.x += p0.x + b0.x; a0.y += p0.y + b0.y; a0.z += p0.z + b0.z; a0.w += p0.w + b0.w;
        a1.x += p1.x + b1.x; a1.y += p1.y + b1.y; a1.z += p1.z + b1.z; a1.w += p1.w + b1.w;
        a2.x += p2.x + b2.x; a2.y += p2.y + b2.y; a2.z += p2.z + b2.z; a2.w += p2.w + b2.w;
        a3.x += p3.x + b3.x; a3.y += p3.y + b3.y; a3.z += p3.z + b3.z; a3.w += p3.w + b3.w;

        o[0 * (FC / 4) + lane] = a0;
        o[1 * (FC / 4) + lane] = a1;
        o[2 * (FC / 4) + lane] = a2;
        o[3 * (FC / 4) + lane] = a3;

        // Cursor self-reset: both warps read cnt before __syncthreads,
        // so resetting after it is safe.
        if (lane == 0) g_cursor[n] = 0;
    }
}

extern "C" void kernel_launch(void* const* d_in, const int* in_sizes, int n_in,
                              void* d_out, int out_size) {
    const float* x         = (const float*)d_in[0];
    const int*   labels    = (const int*)  d_in[1];
    const int*   edge_src  = (const int*)  d_in[2];
    const int*   edge_dst  = (const int*)  d_in[3];
    const int*   edge_prop = (const int*)  d_in[4];
    const float* Pw        = (const float*)d_in[5];
    const float* Pb        = (const float*)d_in[6];
    float*       out       = (float*)d_out;

    const int E = in_sizes[2];   // 640000
    (void)n_in; (void)out_size;

    // grid covers max(E, NF4) = 640000 work items
    k_prep_scatter<<<(NF4 + 255) / 256, 256>>>(edge_src, edge_dst, edge_prop,
                                               labels, Pw, x, E);
    // one node per 64-thread block
    k_gather<<<NN, 64>>>(labels, Pb, out);
}

// round 16
// speedup vs baseline: 1.3341x; 1.3341x over previous
#include <cuda_runtime.h>
#include <cuda_fp16.h>
#include <cuda_bf16.h>

// Rule-indexed sparse graph convolution, round 16 (= exact R10, consolidation).
//   out[n,k,f] = sum_{e: src(e)=n} W[k, lab[src], lab[dst], prop(e)] * x[dst(e), f]
//              + b[k, lab[n], f]
//
// Pipeline (2 launches):
//  1. k_prep_scatter : bucket edges by src (packed rule<<20 | d*32),
//                      transpose Param_W -> float4 PwT, x -> fp16 mirror.
//  2. k_gather : block = 64 = ONE node, 2 warps split the edges (alternating
//                int4 slot groups). Per-edge interleaved load->FMA schedule.
//                NOTE: the slot load at the top of each iteration is the MLP
//                governor — address availability is deliberately NOT decoupled
//                from it (prefetch/batching variants let ptxas front-hoist the
//                random loads and collapse under L1tex queue contention;
//                falsified rounds 13 and 15).
//
// fp16 x path measured at rel_err 1.98e-4 (gate 1e-3).

#define KC 4
#define LC 50
#define PC 16
#define FC 128
#define NN 20000
#define EE 640000
#define LLP (LC * LC * PC)    // 40000, k-stride in Param_W
#define NRULE (LC * LC * PC)  // 40000 rules: (lv*L+lw)*P+p
#define CAP 128               // slots/node; Poisson(32) -> overflow prob ~1e-35
#define NF4 (NN * FC / 4)     // 640000 float4s in x

// ---------- static scratch (allocation-free, zero-initialized) ----------
__device__ int    g_cursor[NN];                    // self-resetting (see k_gather)
__device__ __align__(16) int    g_slot[NN * CAP];  // packed (rule<<20) | (d*32)
__device__ float4 g_PwT[NRULE];                    // {w_k0,w_k1,w_k2,w_k3} per rule
__device__ __align__(16) __half g_xh[NN * FC];     // fp16 mirror of x (5 MB)

// ---------- phase 1: scatter + weight transpose + x->fp16 ----------
__global__ void __launch_bounds__(256)
k_prep_scatter(const int*   __restrict__ edge_src,
               const int*   __restrict__ edge_dst,
               const int*   __restrict__ edge_prop,
               const int*   __restrict__ labels,
               const float* __restrict__ Pw,
               const float* __restrict__ x,
               int E) {
    int t = blockIdx.x * blockDim.x + threadIdx.x;   // grid covers 640000

    // x -> fp16 mirror: float4 -> uint2 of 4 halves, fully coalesced
    if (t < NF4) {
        float4 v = __ldg(&((const float4*)x)[t]);
        __half2 h0 = __floats2half2_rn(v.x, v.y);
        __half2 h1 = __floats2half2_rn(v.z, v.w);
        uint2 pk;
        pk.x = *(unsigned int*)&h0;
        pk.y = *(unsigned int*)&h1;
        ((uint2*)g_xh)[t] = pk;
    }

    // Param_W transpose into float4-per-rule
    if (t < NRULE / 4) {
        const float4* Pw4 = (const float4*)Pw;
        float4 w0 = __ldg(&Pw4[t]);                 // k=0
        float4 w1 = __ldg(&Pw4[t + LLP / 4]);       // k=1
        float4 w2 = __ldg(&Pw4[t + 2 * LLP / 4]);   // k=2
        float4 w3 = __ldg(&Pw4[t + 3 * LLP / 4]);   // k=3
        int b = t * 4;
        g_PwT[b + 0] = make_float4(w0.x, w1.x, w2.x, w3.x);
        g_PwT[b + 1] = make_float4(w0.y, w1.y, w2.y, w3.y);
        g_PwT[b + 2] = make_float4(w0.z, w1.z, w2.z, w3.z);
        g_PwT[b + 3] = make_float4(w0.w, w1.w, w2.w, w3.w);
    }

    // edge bucketing (cursors start at zero via the self-reset invariant)
    if (t < E) {
        int s  = edge_src[t];
        int d  = edge_dst[t];
        int p  = edge_prop[t];
        int lw = __ldg(&labels[d]);
        // rule<<20 | d*32 : rule < 800 (10b), d*32 < 640000 (20b)
        int pk = ((lw * PC + p) << 20) | (d << 5);
        int pos = atomicAdd(&g_cursor[s], 1);
        if (pos < CAP) g_slot[s * CAP + pos] = pk;
    }
}

// ---------- phase 2: gather, block = one node, 2 edge-split warps ----------
__global__ void __launch_bounds__(64, 24)
k_gather(const int*   __restrict__ labels,
         const float* __restrict__ Pb,
         float*       __restrict__ out) {
    int tid  = threadIdx.x;
    int lane = tid & 31;
    int half = tid >> 5;               // 0 or 1
    int n    = blockIdx.x;             // grid = NN, exact

    __shared__ float4 sacc[4][32];     // [channel][lane], 2 KB

    int lv  = labels[n];               // uniform per warp
    int cnt = g_cursor[n];
    if (cnt > CAP) cnt = CAP;

    const int4*  slots4 = (const int4*)(g_slot + n * CAP);   // 16B aligned
    const uint2* xh     = (const uint2*)g_xh + lane;  // + (d*32) per row

    float4 a0 = make_float4(0.f, 0.f, 0.f, 0.f);
    float4 a1 = a0, a2 = a0, a3 = a0;

    const float4* PwTlv = g_PwT + lv * (LC * PC);   // + (lw*PC+p)

#define ACC_EDGE(W, RAW)                                                        \
    {                                                                           \
        float2 lo = __half22float2(*(__half2*)&(RAW).x);                        \
        float2 hi = __half22float2(*(__half2*)&(RAW).y);                        \
        a0.x += (W).x * lo.x; a0.y += (W).x * lo.y; a0.z += (W).x * hi.x; a0.w += (W).x * hi.y; \
        a1.x += (W).y * lo.x; a1.y += (W).y * lo.y; a1.z += (W).y * hi.x; a1.w += (W).y * hi.y; \
        a2.x += (W).z * lo.x; a2.y += (W).z * lo.y; a2.z += (W).z * hi.x; a2.w += (W).z * hi.y; \
        a3.x += (W).w * lo.x; a3.y += (W).w * lo.y; a3.z += (W).w * hi.x; a3.w += (W).w * hi.y; \
    }

    int nG = cnt >> 2;                 // int4 groups of 4 edges
    for (int g = half; g < nG; g += 2) {
        int4 pk = slots4[g];           // MLP governor: addresses exist only
                                       // after this load returns
        int o0 = pk.x & 0xFFFFF; unsigned r0 = ((unsigned)pk.x) >> 20;
        int o1 = pk.y & 0xFFFFF; unsigned r1 = ((unsigned)pk.y) >> 20;
        int o2 = pk.z & 0xFFFFF; unsigned r2 = ((unsigned)pk.z) >> 20;
        int o3 = pk.w & 0xFFFFF; unsigned r3 = ((unsigned)pk.w) >> 20;

        float4 w0 = __ldg(&PwTlv[r0]);
        uint2  v0 = __ldg(&xh[o0]);
        ACC_EDGE(w0, v0)
        float4 w1 = __ldg(&PwTlv[r1]);
        uint2  v1 = __ldg(&xh[o1]);
        ACC_EDGE(w1, v1)
        float4 w2 = __ldg(&PwTlv[r2]);
        uint2  v2 = __ldg(&xh[o2]);
        ACC_EDGE(w2, v2)
        float4 w3 = __ldg(&PwTlv[r3]);
        uint2  v3 = __ldg(&xh[o3]);
        ACC_EDGE(w3, v3)
    }
    if (half == 1) {                   // tail edges (cnt % 4) handled by warp 1
        for (int i = nG << 2; i < cnt; ++i) {
            int pw = g_slot[n * CAP + i];
            int o0 = pw & 0xFFFFF; unsigned r0 = ((unsigned)pw) >> 20;
            float4 w0 = __ldg(&PwTlv[r0]);
            uint2  v0 = __ldg(&xh[o0]);
            ACC_EDGE(w0, v0)
        }
    }
#undef ACC_EDGE

    // Combine: warp 1 -> smem, sync, warp 0 adds + bias + stores.
    if (half == 1) {
        sacc[0][lane] = a0;
        sacc[1][lane] = a1;
        sacc[2][lane] = a2;
        sacc[3][lane] = a3;
    }
    __syncthreads();

    if (half == 0) {
        float4 p0 = sacc[0][lane];
        float4 p1 = sacc[1][lane];
        float4 p2 = sacc[2][lane];
        float4 p3 = sacc[3][lane];

        const float4* pb = (const float4*)Pb;
        float4*       o  = (float4*)(out + (size_t)n * (KC * FC));

        float4 b0 = __ldg(&pb[(0 * LC + lv) * (FC / 4) + lane]);
        float4 b1 = __ldg(&pb[(1 * LC + lv) * (FC / 4) + lane]);
        float4 b2 = __ldg(&pb[(2 * LC + lv) * (FC / 4) + lane]);
        float4 b3 = __ldg(&pb[(3 * LC + lv) * (FC / 4) + lane]);

        a0.x += p0.x + b0.x; a0.y += p0.y + b0.y; a0.z += p0.z + b0.z; a0.w += p0.w + b0.w;
        a1.x += p1.x + b1.x; a1.y += p1.y + b1.y; a1.z += p1.z + b1.z; a1.w += p1.w + b1.w;
        a2.x += p2.x + b2.x; a2.y += p2.y + b2.y; a2.z += p2.z + b2.z; a2.w += p2.w + b2.w;
        a3.x += p3.x + b3.x; a3.y += p3.y + b3.y; a3.z += p3.z + b3.z; a3.w += p3.w + b3.w;

        o[0 * (FC / 4) + lane] = a0;
        o[1 * (FC / 4) + lane] = a1;
        o[2 * (FC / 4) + lane] = a2;
        o[3 * (FC / 4) + lane] = a3;

        // Cursor self-reset: both warps read cnt before __syncthreads,
        // so resetting after it is safe.
        if (lane == 0) g_cursor[n] = 0;
    }
}

extern "C" void kernel_launch(void* const* d_in, const int* in_sizes, int n_in,
                              void* d_out, int out_size) {
    const float* x         = (const float*)d_in[0];
    const int*   labels    = (const int*)  d_in[1];
    const int*   edge_src  = (const int*)  d_in[2];
    const int*   edge_dst  = (const int*)  d_in[3];
    const int*   edge_prop = (const int*)  d_in[4];
    const float* Pw        = (const float*)d_in[5];
    const float* Pb        = (const float*)d_in[6];
    float*       out       = (float*)d_out;

    const int E = in_sizes[2];   // 640000
    (void)n_in; (void)out_size;

    // grid covers max(E, NF4) = 640000 work items
    k_prep_scatter<<<(NF4 + 255) / 256, 256>>>(edge_src, edge_dst, edge_prop,
                                               labels, Pw, x, E);
    // one node per 64-thread block
    k_gather<<<NN, 64>>>(labels, Pb, out);
}